// round 13
// baseline (speedup 1.0000x reference)
#include <cuda_runtime.h>
#include <cuda_bf16.h>
#include <cstdint>

// Problem constants
#define NB 32768   // number of signals (B)
#define NA 512     // number of atoms (N)
#define MD 64      // embedding dim (M)
#define SP 5       // sparsity
#define ZELEMS 2097152        // 32*64*32*32
#define LOSS_OFF ZELEMS       // loss scalar offset in d_out
#define COEF_OFF (ZELEMS + 1) // coefficients offset in d_out

// Scratch (static __device__ — no allocation allowed)
__device__ float g_Zt[NB * MD];   // Z transposed: [j][m], 8 MB
__device__ float g_H[NB * NA];    // h_bar: [j][n], 64 MB (keep L2-warm)
__device__ float g_G[NA * NA];    // Gram D^T D, 1 MB
__device__ float g_Dt[NA * MD];   // D transposed: [n][m], 128 KB
// bf16 3-way-split operands, pre-swizzled rows of 128 B
__device__ __align__(16) __nv_bfloat16 g_A[3][NB * MD];
__device__ __align__(16) __nv_bfloat16 g_B[3][NA * MD];

__host__ __device__ __forceinline__ uint32_t sw128(uint32_t o) {
    return o ^ ((o >> 3) & 0x70);
}
__device__ __forceinline__ uint32_t smem_u32(const void* p) {
    uint32_t a;
    asm("{ .reg .u64 t; cvta.to.shared.u64 t, %1; cvt.u32.u64 %0, t; }"
        : "=r"(a) : "l"(p));
    return a;
}
__device__ __forceinline__ uint32_t swaddr(uint32_t base, int row, int colbyte) {
    uint32_t o = (uint32_t)(row * 128 + colbyte);
    return base + (o ^ ((uint32_t)(row & 7) << 4));
}

// ---------------------------------------------------------------------------
// k_zero: zero the loss slot + coefficient region of d_out (side stream).
// ---------------------------------------------------------------------------
__global__ void k_zero(float* __restrict__ out, int nfloats) {
    int tid = blockIdx.x * blockDim.x + threadIdx.x;
    float4* p = (float4*)(out + LOSS_OFF);
    int n4 = nfloats >> 2;
    float4 z4 = make_float4(0.f, 0.f, 0.f, 0.f);
    for (int i = tid; i < n4; i += gridDim.x * blockDim.x) __stcs(p + i, z4);
    if (blockIdx.x == 0 && threadIdx.x < (nfloats & 3))
        out[LOSS_OFF + (n4 << 2) + threadIdx.x] = 0.f;
}

// ---------------------------------------------------------------------------
// k_prepD: Dt transpose + B split (tid < 32768) and Gram tiles (all 256 blocks).
// ---------------------------------------------------------------------------
__global__ void k_prepD(const float* __restrict__ D) {
    __shared__ float Da[32 * 65];
    __shared__ float Db[32 * 65];
    int tid = blockIdx.x * blockDim.x + threadIdx.x;

    if (tid < MD * NA) {
        int m = tid >> 9;
        int n = tid & (NA - 1);
        float v = D[tid];
        g_Dt[n * MD + m] = v;
        __nv_bfloat16 bh = __float2bfloat16(v);
        float r1 = v - __bfloat162float(bh);
        __nv_bfloat16 bm = __float2bfloat16(r1);
        float r2 = r1 - __bfloat162float(bm);
        __nv_bfloat16 bl = __float2bfloat16(r2);
        uint32_t so = sw128((uint32_t)(n * 128 + m * 2));
        *(__nv_bfloat16*)((char*)g_B[0] + so) = bh;
        *(__nv_bfloat16*)((char*)g_B[1] + so) = bm;
        *(__nv_bfloat16*)((char*)g_B[2] + so) = bl;
    }

    // Gram tile per block (256 blocks = 16x16 tiles)
    {
        int a0 = (blockIdx.x >> 4) * 32, b0 = (blockIdx.x & 15) * 32;
        int t = threadIdx.x;  // 256
#pragma unroll
        for (int it = 0; it < 8; it++) {
            int e = t + it * 256;
            int aa = e & 31, m = e >> 5;
            Da[aa * 65 + m] = D[m * NA + a0 + aa];
            Db[aa * 65 + m] = D[m * NA + b0 + aa];
        }
        __syncthreads();
        int tb = t & 15, ta = t >> 4;
        float acc[2][2] = {};
#pragma unroll
        for (int m = 0; m < MD; m++) {
            float a0v = Da[(2 * ta) * 65 + m];
            float a1v = Da[(2 * ta + 1) * 65 + m];
            float b0v = Db[(2 * tb) * 65 + m];
            float b1v = Db[(2 * tb + 1) * 65 + m];
            acc[0][0] += a0v * b0v; acc[0][1] += a0v * b1v;
            acc[1][0] += a1v * b0v; acc[1][1] += a1v * b1v;
        }
#pragma unroll
        for (int i = 0; i < 2; i++)
#pragma unroll
            for (int l = 0; l < 2; l++)
                g_G[(a0 + 2 * ta + i) * NA + (b0 + 2 * tb + l)] = acc[i][l];
    }
}

// ---------------------------------------------------------------------------
// Fused scatter + bf16 split.
// Inverse map: for f = m*32768+j,  g = (m>>1)<<16 | (j&63)<<10 | (m&1)<<9
//                                      | ((j>>11)&15)<<5 | ((j>>6)&31)
// ---------------------------------------------------------------------------
__global__ void k_ssplit(const float* __restrict__ ze) {
    int t = blockIdx.x * blockDim.x + threadIdx.x;  // 262144
    int lane = t & 31;
    int grp = (t >> 5) & 7;         // m-group of 8
    int jlow6 = (t >> 8) & 63;      // c
    int jhi4 = t >> 14;             // j>>11
    int j = (jhi4 << 11) | (lane << 6) | jlow6;

    int base_g = ((grp * 4) << 16) | (jlow6 << 10) | (jhi4 << 5) | lane;
    float v[8];
#pragma unroll
    for (int e = 0; e < 8; e++)
        v[e] = __ldcs(ze + base_g + ((e >> 1) << 16) + ((e & 1) << 9));

    float4* zt4 = (float4*)(g_Zt + j * MD + grp * 8);
    zt4[0] = make_float4(v[0], v[1], v[2], v[3]);
    zt4[1] = make_float4(v[4], v[5], v[6], v[7]);

    unsigned short hs[8], ms[8], ls[8];
#pragma unroll
    for (int i = 0; i < 8; i++) {
        __nv_bfloat16 bh = __float2bfloat16(v[i]);
        float r1 = v[i] - __bfloat162float(bh);
        __nv_bfloat16 bm = __float2bfloat16(r1);
        float r2 = r1 - __bfloat162float(bm);
        __nv_bfloat16 bl = __float2bfloat16(r2);
        hs[i] = __bfloat16_as_ushort(bh);
        ms[i] = __bfloat16_as_ushort(bm);
        ls[i] = __bfloat16_as_ushort(bl);
    }
    int tile = j >> 7, r = j & 127;
    uint32_t so = sw128((uint32_t)(r * 128 + grp * 16));
    size_t off = (size_t)tile * 16384 + so;
    *(uint4*)((char*)g_A[0] + off) =
        make_uint4(hs[0] | (hs[1] << 16), hs[2] | (hs[3] << 16),
                   hs[4] | (hs[5] << 16), hs[6] | (hs[7] << 16));
    *(uint4*)((char*)g_A[1] + off) =
        make_uint4(ms[0] | (ms[1] << 16), ms[2] | (ms[3] << 16),
                   ms[4] | (ms[5] << 16), ms[6] | (ms[7] << 16));
    *(uint4*)((char*)g_A[2] + off) =
        make_uint4(ls[0] | (ls[1] << 16), ls[2] | (ls[3] << 16),
                   ls[4] | (ls[5] << 16), ls[6] | (ls[7] << 16));
}

// ---------------------------------------------------------------------------
// HMMA GEMM, 3-way bf16 split, gray-code product order.
// Block: 128 j x 64 n (smem 72 KB -> 3 blocks/SM, 24 warps). 8 warps:
// warpm = wid&3 (32 rows), warpn = wid>>2 (32 cols). 2x4 m16n8 tiles/warp.
// ---------------------------------------------------------------------------
#define GEMM_SMEM (49152 + 3 * 8192)
__global__ __launch_bounds__(256, 3) void k_gemm_mma() {
    extern __shared__ char smem[];
    uint32_t sb = smem_u32(smem);
    int tid = threadIdx.x;
    int wid = tid >> 5, lane = tid & 31;
    int j0 = blockIdx.x * 128;
    int n0 = blockIdx.y * 64;

#pragma unroll
    for (int p = 0; p < 3; p++) {
        const uint4* srcA = (const uint4*)g_A[p] + blockIdx.x * 1024;
        uint4* dstA = (uint4*)(smem + p * 16384);
        const uint4* srcB = (const uint4*)g_B[p] + blockIdx.y * 512;
        uint4* dstB = (uint4*)(smem + 49152 + p * 8192);
#pragma unroll
        for (int it = 0; it < 4; it++)
            dstA[tid + it * 256] = srcA[tid + it * 256];
#pragma unroll
        for (int it = 0; it < 2; it++)
            dstB[tid + it * 256] = srcB[tid + it * 256];
    }
    __syncthreads();

    int warpm = wid & 3, warpn = wid >> 2;
    float acc[2][4][4] = {};

    const int GA[6] = {0, 0, 1, 1, 0, 2};
    const int GB[6] = {2, 1, 1, 0, 0, 0};

#pragma unroll
    for (int k = 0; k < 64; k += 16) {
        uint32_t a[2][4];
        uint32_t b[4][2];
#pragma unroll
        for (int s = 0; s < 6; s++) {
            if (s == 0 || GA[s] != GA[s - 1]) {
                uint32_t aBase = sb + GA[s] * 16384;
#pragma unroll
                for (int mt = 0; mt < 2; mt++) {
                    int arow = warpm * 32 + mt * 16 + (lane & 15);
                    int acol = k + ((lane >> 4) << 3);
                    uint32_t addr = swaddr(aBase, arow, acol * 2);
                    asm volatile(
                        "ldmatrix.sync.aligned.m8n8.x4.shared.b16 {%0,%1,%2,%3}, [%4];"
                        : "=r"(a[mt][0]), "=r"(a[mt][1]), "=r"(a[mt][2]),
                          "=r"(a[mt][3])
                        : "r"(addr));
                }
            }
            if (s == 0 || GB[s] != GB[s - 1]) {
                uint32_t bBase = sb + 49152 + GB[s] * 8192;
#pragma unroll
                for (int np = 0; np < 2; np++) {
                    int brow = warpn * 32 + np * 16 + ((lane >> 4) << 3) + (lane & 7);
                    int bcol = k + (((lane >> 3) & 1) << 3);
                    uint32_t addr = swaddr(bBase, brow, bcol * 2);
                    uint32_t r0, r1, r2, r3;
                    asm volatile(
                        "ldmatrix.sync.aligned.m8n8.x4.shared.b16 {%0,%1,%2,%3}, [%4];"
                        : "=r"(r0), "=r"(r1), "=r"(r2), "=r"(r3) : "r"(addr));
                    b[np * 2][0] = r0;     b[np * 2][1] = r1;
                    b[np * 2 + 1][0] = r2; b[np * 2 + 1][1] = r3;
                }
            }
#pragma unroll
            for (int mt = 0; mt < 2; mt++)
#pragma unroll
                for (int nt = 0; nt < 4; nt++) {
                    asm volatile(
                        "mma.sync.aligned.m16n8k16.row.col.f32.bf16.bf16.f32 "
                        "{%0,%1,%2,%3}, {%4,%5,%6,%7}, {%8,%9}, {%0,%1,%2,%3};"
                        : "+f"(acc[mt][nt][0]), "+f"(acc[mt][nt][1]),
                          "+f"(acc[mt][nt][2]), "+f"(acc[mt][nt][3])
                        : "r"(a[mt][0]), "r"(a[mt][1]), "r"(a[mt][2]),
                          "r"(a[mt][3]), "r"(b[nt][0]), "r"(b[nt][1]));
                }
        }
    }

    int rbase = j0 + warpm * 32 + (lane >> 2);
    int cbase = n0 + warpn * 32 + (lane & 3) * 2;
#pragma unroll
    for (int mt = 0; mt < 2; mt++)
#pragma unroll
        for (int nt = 0; nt < 4; nt++) {
            int r = rbase + mt * 16;
            int c = cbase + nt * 8;
            *(float2*)&g_H[(size_t)r * NA + c] =
                make_float2(acc[mt][nt][0], acc[mt][nt][1]);
            *(float2*)&g_H[(size_t)(r + 8) * NA + c] =
                make_float2(acc[mt][nt][2], acc[mt][nt][3]);
        }
}

// ---------------------------------------------------------------------------
// OMP, incremental-residual (unchanged from R11 best).
// ---------------------------------------------------------------------------
__global__ __launch_bounds__(256, 4) void k_omp(float* __restrict__ out) {
    __shared__ float sC[8][3 * NA];  // c_1..c_3 per warp: 48 KB
    __shared__ float bsum[8];
    int warp = threadIdx.x >> 5;
    int lane = threadIdx.x & 31;
    int j = blockIdx.x * 8 + warp;
    float* cw = sC[warp];
    float4* cw4 = (float4*)cw;

    float4 h4[4];
    const float4* hrow4 = (const float4*)(g_H + (size_t)j * NA);
    float lmax = 0.0f;
#pragma unroll
    for (int q = 0; q < 4; q++) {
        h4[q] = hrow4[lane + 32 * q];
        lmax = fmaxf(lmax, fmaxf(fmaxf(fabsf(h4[q].x), fabsf(h4[q].y)),
                                 fmaxf(fabsf(h4[q].z), fabsf(h4[q].w))));
    }

    float L[SP][SP];
    float rinv[SP];
    float y[SP];
    float x[SP];
    int I[SP];
    unsigned mask16 = 0;

#pragma unroll
    for (int k = 1; k <= SP; k++) {
        float vmax = __uint_as_float(
            __reduce_max_sync(0xFFFFFFFFu, __float_as_uint(lmax)));

        unsigned eq = 0;
#pragma unroll
        for (int q = 0; q < 4; q++) {
            if (fabsf(h4[q].x) == vmax) eq |= 1u << (4 * q + 0);
            if (fabsf(h4[q].y) == vmax) eq |= 1u << (4 * q + 1);
            if (fabsf(h4[q].z) == vmax) eq |= 1u << (4 * q + 2);
            if (fabsf(h4[q].w) == vmax) eq |= 1u << (4 * q + 3);
        }
        int b = __ffs(eq | 0x10000u) - 1;
        int ncand = eq ? ((lane << 2) | ((b >> 2) << 7) | (b & 3)) : 0x7FFFFFFF;
        int bestn = __reduce_min_sync(0xFFFFFFFFu, ncand);
        I[k - 1] = bestn;

        float g45 = 0.0f;
        if (k == SP) g45 = __ldg(g_G + (size_t)I[3] * NA + bestn);

        float4 m0x = (b & 4) ? h4[1] : h4[0];
        float4 m1x = (b & 4) ? h4[3] : h4[2];
        float4 mm = (b & 8) ? m1x : m0x;
        float p0 = (b & 1) ? mm.y : mm.x;
        float p1 = (b & 1) ? mm.w : mm.z;
        float hown = (b & 2) ? p1 : p0;
        float hsel = __shfl_sync(0xFFFFFFFFu, hown, (bestn >> 2) & 31);

        float cb[4];
#pragma unroll
        for (int jj = 0; jj < 3; jj++)
            if (jj < k - 1) cb[jj] = cw[jj * NA + bestn];
        if (k == SP)
            cb[3] = (g45 - L[3][0] * cb[0] - L[3][1] * cb[1] -
                     L[3][2] * cb[2]) * rinv[3];

        float hbk = hsel;
#pragma unroll
        for (int jj = 0; jj < 4; jj++)
            if (jj < k - 1) hbk += y[jj] * cb[jj];

        if (k == 1) {
            L[0][0] = 1.0f;
            rinv[0] = 1.0f;
        } else {
            float w[SP - 1];
            float ss = 0.0f;
#pragma unroll
            for (int i = 0; i < SP - 1; i++) {
                if (i < k - 1) {
                    float gvi = 0.0f;
#pragma unroll
                    for (int jj = 0; jj < SP - 1; jj++)
                        if (jj <= i) gvi += L[i][jj] * cb[jj];
                    float s = gvi;
#pragma unroll
                    for (int j2 = 0; j2 < SP - 1; j2++)
                        if (j2 < i) s -= L[i][j2] * w[j2];
                    w[i] = s * rinv[i];
                    ss += w[i] * w[i];
                }
            }
#pragma unroll
            for (int j2 = 0; j2 < SP - 1; j2++)
                if (j2 < k - 1) L[k - 1][j2] = w[j2];
            float v = fmaxf(1.0f - ss, 0.0f);
            float rs = rsqrtf(v);
            L[k - 1][k - 1] = v * rs;
            rinv[k - 1] = rs;
        }

        {
            float s = hbk;
#pragma unroll
            for (int j2 = 0; j2 < SP - 1; j2++)
                if (j2 < k - 1) s -= L[k - 1][j2] * y[j2];
            y[k - 1] = s * rinv[k - 1];
        }

        if (((bestn >> 2) & 31) == lane)
            mask16 |= 1u << (((bestn >> 7) << 2) | (bestn & 3));

        if (k < SP) {
            const float4* grow4 = (const float4*)(g_G + (size_t)bestn * NA);
            float yk = y[k - 1];
            float rk = rinv[k - 1];
            lmax = 0.0f;
#pragma unroll
            for (int q = 0; q < 4; q++) {
                float4 c4 = grow4[lane + 32 * q];
#pragma unroll
                for (int jj = 0; jj < 3; jj++) {
                    if (jj < k - 1) {
                        float lkj = L[k - 1][jj];
                        float4 cj = cw4[jj * 128 + lane + 32 * q];
                        c4.x -= lkj * cj.x; c4.y -= lkj * cj.y;
                        c4.z -= lkj * cj.z; c4.w -= lkj * cj.w;
                    }
                }
                c4.x *= rk; c4.y *= rk; c4.z *= rk; c4.w *= rk;
                if (k - 1 < 3) cw4[(k - 1) * 128 + lane + 32 * q] = c4;
                float4 hh = h4[q];
                hh.x -= yk * c4.x; hh.y -= yk * c4.y;
                hh.z -= yk * c4.z; hh.w -= yk * c4.w;
                if ((mask16 >> (q * 4 + 0)) & 1u) hh.x = 0.0f;
                if ((mask16 >> (q * 4 + 1)) & 1u) hh.y = 0.0f;
                if ((mask16 >> (q * 4 + 2)) & 1u) hh.z = 0.0f;
                if ((mask16 >> (q * 4 + 3)) & 1u) hh.w = 0.0f;
                h4[q] = hh;
                lmax = fmaxf(lmax, fmaxf(fmaxf(fabsf(hh.x), fabsf(hh.y)),
                                         fmaxf(fabsf(hh.z), fabsf(hh.w))));
            }
            __syncwarp();
        }
    }

#pragma unroll
    for (int i = SP - 1; i >= 0; i--) {
        float s = y[i];
#pragma unroll
        for (int j2 = i + 1; j2 < SP; j2++) s -= L[j2][i] * x[j2];
        x[i] = s * rinv[i];
    }

    float ze0 = g_Zt[j * MD + lane];
    float ze1 = g_Zt[j * MD + 32 + lane];
    float r0 = 0.f, r1 = 0.f;
#pragma unroll
    for (int i = 0; i < SP; i++) {
        const float* dcol = g_Dt + I[i] * MD;
        r0 += x[i] * dcol[lane];
        r1 += x[i] * dcol[32 + lane];
    }

#pragma unroll
    for (int p = 0; p < 2; p++) {
        int m = lane + 32 * p;
        float rm = p ? r1 : r0;
        float ze = p ? ze1 : ze0;
        float zo = ze + (rm - ze);
        int f = (m << 15) | j;
        int c = f & 63, ww = (f >> 6) & 31, hh = (f >> 11) & 31, bb = f >> 16;
        __stcs(&out[((bb * 64 + c) * 32 + hh) * 32 + ww], zo);
    }

    float d0 = r0 - ze0, d1 = r1 - ze1;
    float s = d0 * d0 + d1 * d1;
#pragma unroll
    for (int off = 16; off; off >>= 1) s += __shfl_xor_sync(0xFFFFFFFFu, s, off);
    if (lane == 0) bsum[warp] = s;
    __syncthreads();
    if (threadIdx.x == 0) {
        float t = 0.0f;
#pragma unroll
        for (int wq = 0; wq < 8; wq++) t += bsum[wq];
        atomicAdd(out + LOSS_OFF, t * (1.25f / (float)ZELEMS));
    }

    if (lane == 0) {
        float* co = out + COEF_OFF;
        __stcs(&co[(size_t)I[0] * NB + j], x[0]);
        __stcs(&co[(size_t)I[1] * NB + j], x[1]);
        __stcs(&co[(size_t)I[2] * NB + j], x[2]);
        __stcs(&co[(size_t)I[3] * NB + j], x[3]);
        __stcs(&co[(size_t)I[4] * NB + j], x[4]);
    }
}

// ---------------------------------------------------------------------------
// Launch: main chain on a CREATED stream (s3); legacy stream 0 only forks at
// entry and joins at exit so its implicit-sync semantics add no false deps.
// ---------------------------------------------------------------------------
extern "C" void kernel_launch(void* const* d_in, const int* in_sizes, int n_in,
                              void* d_out, int out_size) {
    const float* ze = (const float*)d_in[0];  // (32, 64, 32, 32)
    const float* D = (const float*)d_in[1];   // (64, 512)
    float* out = (float*)d_out;

    static cudaStream_t s1 = nullptr, s2 = nullptr, s3 = nullptr;
    static cudaEvent_t e0 = nullptr, ez = nullptr, es = nullptr, ef = nullptr;
    static bool init_done = false;
    if (!init_done) {
        cudaStreamCreateWithFlags(&s1, cudaStreamNonBlocking);
        cudaStreamCreateWithFlags(&s2, cudaStreamNonBlocking);
        cudaStreamCreateWithFlags(&s3, cudaStreamNonBlocking);
        cudaEventCreateWithFlags(&e0, cudaEventDisableTiming);
        cudaEventCreateWithFlags(&ez, cudaEventDisableTiming);
        cudaEventCreateWithFlags(&es, cudaEventDisableTiming);
        cudaEventCreateWithFlags(&ef, cudaEventDisableTiming);
        cudaFuncSetAttribute(k_gemm_mma,
                             cudaFuncAttributeMaxDynamicSharedMemorySize,
                             GEMM_SMEM);
        init_done = true;
    }

    int ztail = out_size - LOSS_OFF;  // loss + coefficients

    // fork from the capture-origin stream
    cudaEventRecord(e0, 0);
    cudaStreamWaitEvent(s1, e0, 0);
    cudaStreamWaitEvent(s2, e0, 0);
    cudaStreamWaitEvent(s3, e0, 0);

    // s1: big output zeroing (only k_omp depends on it)
    k_zero<<<4096, 256, 0, s1>>>(out, ztail);
    cudaEventRecord(ez, s1);

    // s2: z_e scatter + A split (k_gemm depends on it)
    k_ssplit<<<1024, 256, 0, s2>>>(ze);
    cudaEventRecord(es, s2);

    // s3 (main): D-derived prep -> GEMM -> OMP
    k_prepD<<<256, 256, 0, s3>>>(D);
    cudaStreamWaitEvent(s3, es, 0);
    k_gemm_mma<<<dim3(NB / 128, NA / 64), 256, GEMM_SMEM, s3>>>();
    cudaStreamWaitEvent(s3, ez, 0);
    k_omp<<<NB / 8, 256, 0, s3>>>(out);

    // join back into the capture-origin stream
    cudaEventRecord(ef, s3);
    cudaStreamWaitEvent(0, ef, 0);
}

// round 15
// speedup vs baseline: 1.2160x; 1.2160x over previous
#include <cuda_runtime.h>
#include <cuda_bf16.h>
#include <cstdint>

// Problem constants
#define NB 32768   // number of signals (B)
#define NA 512     // number of atoms (N)
#define MD 64      // embedding dim (M)
#define SP 5       // sparsity
#define ZELEMS 2097152        // 32*64*32*32
#define LOSS_OFF ZELEMS       // loss scalar offset in d_out
#define COEF_OFF (ZELEMS + 1) // coefficients offset in d_out

// Scratch (static __device__ — no allocation allowed)
__device__ float g_Zt[NB * MD];   // Z transposed: [j][m], 8 MB
__device__ float g_H[NB * NA];    // h_bar: [j][n], 64 MB (keep L2-warm)
__device__ float g_G[NA * NA];    // Gram D^T D, 1 MB
__device__ float g_Dt[NA * MD];   // D transposed: [n][m], 128 KB
// bf16 3-way-split operands, pre-swizzled rows of 128 B
__device__ __align__(16) __nv_bfloat16 g_A[3][NB * MD];
__device__ __align__(16) __nv_bfloat16 g_B[3][NA * MD];

__host__ __device__ __forceinline__ uint32_t sw128(uint32_t o) {
    return o ^ ((o >> 3) & 0x70);
}
__device__ __forceinline__ uint32_t smem_u32(const void* p) {
    uint32_t a;
    asm("{ .reg .u64 t; cvta.to.shared.u64 t, %1; cvt.u32.u64 %0, t; }"
        : "=r"(a) : "l"(p));
    return a;
}
__device__ __forceinline__ uint32_t swaddr(uint32_t base, int row, int colbyte) {
    uint32_t o = (uint32_t)(row * 128 + colbyte);
    return base + (o ^ ((uint32_t)(row & 7) << 4));
}

// ---------------------------------------------------------------------------
// k_prepD: Dt transpose + B split (tid < 32768), Gram tiles (256 blocks),
// and the non-multiple-of-4 tail of the output zero region.
// ---------------------------------------------------------------------------
__global__ void k_prepD(const float* __restrict__ D, float* __restrict__ out,
                        int ztail) {
    __shared__ float Da[32 * 65];
    __shared__ float Db[32 * 65];
    int tid = blockIdx.x * blockDim.x + threadIdx.x;

    // tail elements not covered by the float4 zeroing in k_gemm_mma
    if (blockIdx.x == 0 && threadIdx.x < (ztail & 3))
        out[LOSS_OFF + (ztail & ~3) + threadIdx.x] = 0.f;

    if (tid < MD * NA) {
        int m = tid >> 9;
        int n = tid & (NA - 1);
        float v = D[tid];
        g_Dt[n * MD + m] = v;
        __nv_bfloat16 bh = __float2bfloat16(v);
        float r1 = v - __bfloat162float(bh);
        __nv_bfloat16 bm = __float2bfloat16(r1);
        float r2 = r1 - __bfloat162float(bm);
        __nv_bfloat16 bl = __float2bfloat16(r2);
        uint32_t so = sw128((uint32_t)(n * 128 + m * 2));
        *(__nv_bfloat16*)((char*)g_B[0] + so) = bh;
        *(__nv_bfloat16*)((char*)g_B[1] + so) = bm;
        *(__nv_bfloat16*)((char*)g_B[2] + so) = bl;
    }

    // Gram tile per block (256 blocks = 16x16 tiles)
    {
        int a0 = (blockIdx.x >> 4) * 32, b0 = (blockIdx.x & 15) * 32;
        int t = threadIdx.x;  // 256
#pragma unroll
        for (int it = 0; it < 8; it++) {
            int e = t + it * 256;
            int aa = e & 31, m = e >> 5;
            Da[aa * 65 + m] = D[m * NA + a0 + aa];
            Db[aa * 65 + m] = D[m * NA + b0 + aa];
        }
        __syncthreads();
        int tb = t & 15, ta = t >> 4;
        float acc[2][2] = {};
#pragma unroll
        for (int m = 0; m < MD; m++) {
            float a0v = Da[(2 * ta) * 65 + m];
            float a1v = Da[(2 * ta + 1) * 65 + m];
            float b0v = Db[(2 * tb) * 65 + m];
            float b1v = Db[(2 * tb + 1) * 65 + m];
            acc[0][0] += a0v * b0v; acc[0][1] += a0v * b1v;
            acc[1][0] += a1v * b0v; acc[1][1] += a1v * b1v;
        }
#pragma unroll
        for (int i = 0; i < 2; i++)
#pragma unroll
            for (int l = 0; l < 2; l++)
                g_G[(a0 + 2 * ta + i) * NA + (b0 + 2 * tb + l)] = acc[i][l];
    }
}

// ---------------------------------------------------------------------------
// Fused scatter + bf16 split.
// Inverse map: for f = m*32768+j,  g = (m>>1)<<16 | (j&63)<<10 | (m&1)<<9
//                                      | ((j>>11)&15)<<5 | ((j>>6)&31)
// ---------------------------------------------------------------------------
__global__ void k_ssplit(const float* __restrict__ ze) {
    int t = blockIdx.x * blockDim.x + threadIdx.x;  // 262144
    int lane = t & 31;
    int grp = (t >> 5) & 7;         // m-group of 8
    int jlow6 = (t >> 8) & 63;      // c
    int jhi4 = t >> 14;             // j>>11
    int j = (jhi4 << 11) | (lane << 6) | jlow6;

    int base_g = ((grp * 4) << 16) | (jlow6 << 10) | (jhi4 << 5) | lane;
    float v[8];
#pragma unroll
    for (int e = 0; e < 8; e++)
        v[e] = __ldcs(ze + base_g + ((e >> 1) << 16) + ((e & 1) << 9));

    float4* zt4 = (float4*)(g_Zt + j * MD + grp * 8);
    zt4[0] = make_float4(v[0], v[1], v[2], v[3]);
    zt4[1] = make_float4(v[4], v[5], v[6], v[7]);

    unsigned short hs[8], ms[8], ls[8];
#pragma unroll
    for (int i = 0; i < 8; i++) {
        __nv_bfloat16 bh = __float2bfloat16(v[i]);
        float r1 = v[i] - __bfloat162float(bh);
        __nv_bfloat16 bm = __float2bfloat16(r1);
        float r2 = r1 - __bfloat162float(bm);
        __nv_bfloat16 bl = __float2bfloat16(r2);
        hs[i] = __bfloat16_as_ushort(bh);
        ms[i] = __bfloat16_as_ushort(bm);
        ls[i] = __bfloat16_as_ushort(bl);
    }
    int tile = j >> 7, r = j & 127;
    uint32_t so = sw128((uint32_t)(r * 128 + grp * 16));
    size_t off = (size_t)tile * 16384 + so;
    *(uint4*)((char*)g_A[0] + off) =
        make_uint4(hs[0] | (hs[1] << 16), hs[2] | (hs[3] << 16),
                   hs[4] | (hs[5] << 16), hs[6] | (hs[7] << 16));
    *(uint4*)((char*)g_A[1] + off) =
        make_uint4(ms[0] | (ms[1] << 16), ms[2] | (ms[3] << 16),
                   ms[4] | (ms[5] << 16), ms[6] | (ms[7] << 16));
    *(uint4*)((char*)g_A[2] + off) =
        make_uint4(ls[0] | (ls[1] << 16), ls[2] | (ls[3] << 16),
                   ls[4] | (ls[5] << 16), ls[6] | (ls[7] << 16));
}

// ---------------------------------------------------------------------------
// HMMA GEMM, 3-way bf16 split, gray-code product order (128j x 128n tiles).
// Fused zeroing of [LOSS_OFF, LOSS_OFF+zlen) at the end — float4s based at
// LOSS_OFF, which IS 16B-aligned (COEF_OFF is not; that was the R14 trap).
// ---------------------------------------------------------------------------
__global__ __launch_bounds__(256, 2) void k_gemm_mma(float* __restrict__ out,
                                                     int zlen) {
    extern __shared__ char smem[];
    uint32_t sb = smem_u32(smem);
    int tid = threadIdx.x;
    int wid = tid >> 5, lane = tid & 31;
    int bid = blockIdx.x + blockIdx.y * gridDim.x;
    int j0 = blockIdx.x * 128;
    int n0 = blockIdx.y * 128;

#pragma unroll
    for (int p = 0; p < 3; p++) {
        const uint4* srcA = (const uint4*)g_A[p] + blockIdx.x * 1024;
        uint4* dstA = (uint4*)(smem + p * 16384);
        const uint4* srcB = (const uint4*)g_B[p] + blockIdx.y * 1024;
        uint4* dstB = (uint4*)(smem + 49152 + p * 16384);
#pragma unroll
        for (int it = 0; it < 4; it++) {
            dstA[tid + it * 256] = srcA[tid + it * 256];
            dstB[tid + it * 256] = srcB[tid + it * 256];
        }
    }
    __syncthreads();

    int warpm = wid & 3, warpn = wid >> 2;
    float acc[2][8][4] = {};

    const int GA[6] = {0, 0, 1, 1, 0, 2};
    const int GB[6] = {2, 1, 1, 0, 0, 0};

#pragma unroll
    for (int k = 0; k < 64; k += 16) {
        uint32_t a[2][4];
        uint32_t b[8][2];
#pragma unroll
        for (int s = 0; s < 6; s++) {
            if (s == 0 || GA[s] != GA[s - 1]) {
                uint32_t aBase = sb + GA[s] * 16384;
#pragma unroll
                for (int mt = 0; mt < 2; mt++) {
                    int arow = warpm * 32 + mt * 16 + (lane & 15);
                    int acol = k + ((lane >> 4) << 3);
                    uint32_t addr = swaddr(aBase, arow, acol * 2);
                    asm volatile(
                        "ldmatrix.sync.aligned.m8n8.x4.shared.b16 {%0,%1,%2,%3}, [%4];"
                        : "=r"(a[mt][0]), "=r"(a[mt][1]), "=r"(a[mt][2]),
                          "=r"(a[mt][3])
                        : "r"(addr));
                }
            }
            if (s == 0 || GB[s] != GB[s - 1]) {
                uint32_t bBase = sb + 49152 + GB[s] * 16384;
#pragma unroll
                for (int np = 0; np < 4; np++) {
                    int brow = warpn * 64 + np * 16 + ((lane >> 4) << 3) + (lane & 7);
                    int bcol = k + (((lane >> 3) & 1) << 3);
                    uint32_t addr = swaddr(bBase, brow, bcol * 2);
                    uint32_t r0, r1, r2, r3;
                    asm volatile(
                        "ldmatrix.sync.aligned.m8n8.x4.shared.b16 {%0,%1,%2,%3}, [%4];"
                        : "=r"(r0), "=r"(r1), "=r"(r2), "=r"(r3) : "r"(addr));
                    b[np * 2][0] = r0;     b[np * 2][1] = r1;
                    b[np * 2 + 1][0] = r2; b[np * 2 + 1][1] = r3;
                }
            }
#pragma unroll
            for (int mt = 0; mt < 2; mt++)
#pragma unroll
                for (int nt = 0; nt < 8; nt++) {
                    asm volatile(
                        "mma.sync.aligned.m16n8k16.row.col.f32.bf16.bf16.f32 "
                        "{%0,%1,%2,%3}, {%4,%5,%6,%7}, {%8,%9}, {%0,%1,%2,%3};"
                        : "+f"(acc[mt][nt][0]), "+f"(acc[mt][nt][1]),
                          "+f"(acc[mt][nt][2]), "+f"(acc[mt][nt][3])
                        : "r"(a[mt][0]), "r"(a[mt][1]), "r"(a[mt][2]),
                          "r"(a[mt][3]), "r"(b[nt][0]), "r"(b[nt][1]));
                }
        }
    }

    int rbase = j0 + warpm * 32 + (lane >> 2);
    int cbase = n0 + warpn * 64 + (lane & 3) * 2;
#pragma unroll
    for (int mt = 0; mt < 2; mt++)
#pragma unroll
        for (int nt = 0; nt < 8; nt++) {
            int r = rbase + mt * 16;
            int c = cbase + nt * 8;
            *(float2*)&g_H[(size_t)r * NA + c] =
                make_float2(acc[mt][nt][0], acc[mt][nt][1]);
            *(float2*)&g_H[(size_t)(r + 8) * NA + c] =
                make_float2(acc[mt][nt][2], acc[mt][nt][3]);
        }

    // ---- fused zeroing of loss + coefficient region (aligned at LOSS_OFF;
    // independent HBM writes; completes before k_omp by stream ordering) ----
    {
        float4* p = (float4*)(out + LOSS_OFF);
        int n4 = zlen >> 2;
        float4 z4 = make_float4(0.f, 0.f, 0.f, 0.f);
        int nthreads = gridDim.x * gridDim.y * 256;
        for (int i = bid * 256 + tid; i < n4; i += nthreads) __stcs(p + i, z4);
    }
}

// ---------------------------------------------------------------------------
// OMP, incremental-residual (R11 best, unchanged).
// ---------------------------------------------------------------------------
__global__ __launch_bounds__(256, 4) void k_omp(float* __restrict__ out) {
    __shared__ float sC[8][3 * NA];  // c_1..c_3 per warp: 48 KB
    __shared__ float bsum[8];
    int warp = threadIdx.x >> 5;
    int lane = threadIdx.x & 31;
    int j = blockIdx.x * 8 + warp;
    float* cw = sC[warp];
    float4* cw4 = (float4*)cw;

    float4 h4[4];
    const float4* hrow4 = (const float4*)(g_H + (size_t)j * NA);
    float lmax = 0.0f;
#pragma unroll
    for (int q = 0; q < 4; q++) {
        h4[q] = hrow4[lane + 32 * q];
        lmax = fmaxf(lmax, fmaxf(fmaxf(fabsf(h4[q].x), fabsf(h4[q].y)),
                                 fmaxf(fabsf(h4[q].z), fabsf(h4[q].w))));
    }

    float L[SP][SP];
    float rinv[SP];
    float y[SP];
    float x[SP];
    int I[SP];
    unsigned mask16 = 0;

#pragma unroll
    for (int k = 1; k <= SP; k++) {
        float vmax = __uint_as_float(
            __reduce_max_sync(0xFFFFFFFFu, __float_as_uint(lmax)));

        unsigned eq = 0;
#pragma unroll
        for (int q = 0; q < 4; q++) {
            if (fabsf(h4[q].x) == vmax) eq |= 1u << (4 * q + 0);
            if (fabsf(h4[q].y) == vmax) eq |= 1u << (4 * q + 1);
            if (fabsf(h4[q].z) == vmax) eq |= 1u << (4 * q + 2);
            if (fabsf(h4[q].w) == vmax) eq |= 1u << (4 * q + 3);
        }
        int b = __ffs(eq | 0x10000u) - 1;
        int ncand = eq ? ((lane << 2) | ((b >> 2) << 7) | (b & 3)) : 0x7FFFFFFF;
        int bestn = __reduce_min_sync(0xFFFFFFFFu, ncand);
        I[k - 1] = bestn;

        float g45 = 0.0f;
        if (k == SP) g45 = __ldg(g_G + (size_t)I[3] * NA + bestn);

        float4 m0x = (b & 4) ? h4[1] : h4[0];
        float4 m1x = (b & 4) ? h4[3] : h4[2];
        float4 mm = (b & 8) ? m1x : m0x;
        float p0 = (b & 1) ? mm.y : mm.x;
        float p1 = (b & 1) ? mm.w : mm.z;
        float hown = (b & 2) ? p1 : p0;
        float hsel = __shfl_sync(0xFFFFFFFFu, hown, (bestn >> 2) & 31);

        float cb[4];
#pragma unroll
        for (int jj = 0; jj < 3; jj++)
            if (jj < k - 1) cb[jj] = cw[jj * NA + bestn];
        if (k == SP)
            cb[3] = (g45 - L[3][0] * cb[0] - L[3][1] * cb[1] -
                     L[3][2] * cb[2]) * rinv[3];

        float hbk = hsel;
#pragma unroll
        for (int jj = 0; jj < 4; jj++)
            if (jj < k - 1) hbk += y[jj] * cb[jj];

        if (k == 1) {
            L[0][0] = 1.0f;
            rinv[0] = 1.0f;
        } else {
            float w[SP - 1];
            float ss = 0.0f;
#pragma unroll
            for (int i = 0; i < SP - 1; i++) {
                if (i < k - 1) {
                    float gvi = 0.0f;
#pragma unroll
                    for (int jj = 0; jj < SP - 1; jj++)
                        if (jj <= i) gvi += L[i][jj] * cb[jj];
                    float s = gvi;
#pragma unroll
                    for (int j2 = 0; j2 < SP - 1; j2++)
                        if (j2 < i) s -= L[i][j2] * w[j2];
                    w[i] = s * rinv[i];
                    ss += w[i] * w[i];
                }
            }
#pragma unroll
            for (int j2 = 0; j2 < SP - 1; j2++)
                if (j2 < k - 1) L[k - 1][j2] = w[j2];
            float v = fmaxf(1.0f - ss, 0.0f);
            float rs = rsqrtf(v);
            L[k - 1][k - 1] = v * rs;
            rinv[k - 1] = rs;
        }

        {
            float s = hbk;
#pragma unroll
            for (int j2 = 0; j2 < SP - 1; j2++)
                if (j2 < k - 1) s -= L[k - 1][j2] * y[j2];
            y[k - 1] = s * rinv[k - 1];
        }

        if (((bestn >> 2) & 31) == lane)
            mask16 |= 1u << (((bestn >> 7) << 2) | (bestn & 3));

        if (k < SP) {
            const float4* grow4 = (const float4*)(g_G + (size_t)bestn * NA);
            float yk = y[k - 1];
            float rk = rinv[k - 1];
            lmax = 0.0f;
#pragma unroll
            for (int q = 0; q < 4; q++) {
                float4 c4 = grow4[lane + 32 * q];
#pragma unroll
                for (int jj = 0; jj < 3; jj++) {
                    if (jj < k - 1) {
                        float lkj = L[k - 1][jj];
                        float4 cj = cw4[jj * 128 + lane + 32 * q];
                        c4.x -= lkj * cj.x; c4.y -= lkj * cj.y;
                        c4.z -= lkj * cj.z; c4.w -= lkj * cj.w;
                    }
                }
                c4.x *= rk; c4.y *= rk; c4.z *= rk; c4.w *= rk;
                if (k - 1 < 3) cw4[(k - 1) * 128 + lane + 32 * q] = c4;
                float4 hh = h4[q];
                hh.x -= yk * c4.x; hh.y -= yk * c4.y;
                hh.z -= yk * c4.z; hh.w -= yk * c4.w;
                if ((mask16 >> (q * 4 + 0)) & 1u) hh.x = 0.0f;
                if ((mask16 >> (q * 4 + 1)) & 1u) hh.y = 0.0f;
                if ((mask16 >> (q * 4 + 2)) & 1u) hh.z = 0.0f;
                if ((mask16 >> (q * 4 + 3)) & 1u) hh.w = 0.0f;
                h4[q] = hh;
                lmax = fmaxf(lmax, fmaxf(fmaxf(fabsf(hh.x), fabsf(hh.y)),
                                         fmaxf(fabsf(hh.z), fabsf(hh.w))));
            }
            __syncwarp();
        }
    }

#pragma unroll
    for (int i = SP - 1; i >= 0; i--) {
        float s = y[i];
#pragma unroll
        for (int j2 = i + 1; j2 < SP; j2++) s -= L[j2][i] * x[j2];
        x[i] = s * rinv[i];
    }

    float ze0 = g_Zt[j * MD + lane];
    float ze1 = g_Zt[j * MD + 32 + lane];
    float r0 = 0.f, r1 = 0.f;
#pragma unroll
    for (int i = 0; i < SP; i++) {
        const float* dcol = g_Dt + I[i] * MD;
        r0 += x[i] * dcol[lane];
        r1 += x[i] * dcol[32 + lane];
    }

#pragma unroll
    for (int p = 0; p < 2; p++) {
        int m = lane + 32 * p;
        float rm = p ? r1 : r0;
        float ze = p ? ze1 : ze0;
        float zo = ze + (rm - ze);
        int f = (m << 15) | j;
        int c = f & 63, ww = (f >> 6) & 31, hh = (f >> 11) & 31, bb = f >> 16;
        __stcs(&out[((bb * 64 + c) * 32 + hh) * 32 + ww], zo);
    }

    float d0 = r0 - ze0, d1 = r1 - ze1;
    float s = d0 * d0 + d1 * d1;
#pragma unroll
    for (int off = 16; off; off >>= 1) s += __shfl_xor_sync(0xFFFFFFFFu, s, off);
    if (lane == 0) bsum[warp] = s;
    __syncthreads();
    if (threadIdx.x == 0) {
        float t = 0.0f;
#pragma unroll
        for (int wq = 0; wq < 8; wq++) t += bsum[wq];
        atomicAdd(out + LOSS_OFF, t * (1.25f / (float)ZELEMS));
    }

    if (lane == 0) {
        float* co = out + COEF_OFF;
        __stcs(&co[(size_t)I[0] * NB + j], x[0]);
        __stcs(&co[(size_t)I[1] * NB + j], x[1]);
        __stcs(&co[(size_t)I[2] * NB + j], x[2]);
        __stcs(&co[(size_t)I[3] * NB + j], x[3]);
        __stcs(&co[(size_t)I[4] * NB + j], x[4]);
    }
}

// ---------------------------------------------------------------------------
// Serial default-stream launch (streams regressed in R12/R13).
// ---------------------------------------------------------------------------
extern "C" void kernel_launch(void* const* d_in, const int* in_sizes, int n_in,
                              void* d_out, int out_size) {
    const float* ze = (const float*)d_in[0];  // (32, 64, 32, 32)
    const float* D = (const float*)d_in[1];   // (64, 512)
    float* out = (float*)d_out;

    cudaFuncSetAttribute(k_gemm_mma,
                         cudaFuncAttributeMaxDynamicSharedMemorySize, 98304);

    int ztail = out_size - LOSS_OFF;   // loss + coefficients
    k_prepD<<<256, 256>>>(D, out, ztail);
    k_ssplit<<<1024, 256>>>(ze);
    k_gemm_mma<<<dim3(NB / 128, NA / 128), 256, 98304>>>(out, ztail & ~3);
    k_omp<<<NB / 8, 256>>>(out);
}